// round 14
// baseline (speedup 1.0000x reference)
#include <cuda_runtime.h>
#include <cstdint>

#define FULLMASK 0xffffffffu
using ull = unsigned long long;

constexpr int NN = 22;
constexpr int D  = 64;

// U table: rows 0-2 = w2[t][:] (= W[t] @ a[t,64:]), rows 3-11 = M1[s*3+t][:] (= W[s] @ a[t,:64])
__device__ __align__(16) float g_U[12*64];
__device__ int g_mflag;   // 1 => mask buffer is uint8, 0 => int32

__device__ __forceinline__ ull fma2(ull a, ull b, ull c) {
    ull d; asm("fma.rn.f32x2 %0, %1, %2, %3;" : "=l"(d) : "l"(a), "l"(b), "l"(c)); return d;
}
__device__ __forceinline__ ull add2(ull a, ull b) {
    ull d; asm("add.rn.f32x2 %0, %1, %2;" : "=l"(d) : "l"(a), "l"(b)); return d;
}
__device__ __forceinline__ ull pack2(float v) {
    ull r; asm("mov.b64 %0, {%1, %1};" : "=l"(r) : "f"(v)); return r;
}
__device__ __forceinline__ float lo32(ull v){ return __uint_as_float((unsigned)v); }
__device__ __forceinline__ float hi32(ull v){ return __uint_as_float((unsigned)(v >> 32)); }

__device__ __forceinline__ float dot4(float4 a, float4 b){
    return fmaf(a.w, b.w, fmaf(a.z, b.z, fmaf(a.y, b.y, a.x * b.x)));
}

__device__ __forceinline__ float dot64(const float* __restrict__ x, const float* __restrict__ y) {
    const float4* xp = (const float4*)x;
    const float4* yp = (const float4*)y;
    float a0 = 0.f, a1 = 0.f, a2 = 0.f, a3 = 0.f;
    #pragma unroll
    for (int k = 0; k < 16; ++k) {
        float4 u = __ldg(xp + k), v = __ldg(yp + k);
        a0 = fmaf(u.x, v.x, a0); a1 = fmaf(u.y, v.y, a1);
        a2 = fmaf(u.z, v.z, a2); a3 = fmaf(u.w, v.w, a3);
    }
    return (a0 + a1) + (a2 + a3);
}

// ================= prep: 6 blocks x 128, one thread per U entry =================
__global__ __launch_bounds__(128) void hetgat_prep(
    const float* __restrict__ W, const float* __restrict__ a,
    const void* __restrict__ maskp)
{
    const int tid = threadIdx.x;
    const int idx = blockIdx.x * 128 + tid;

    if (blockIdx.x == 0 && tid < 32) {
        const int* mi = (const int*)maskp;
        unsigned v0 = (unsigned)__ldg(mi + tid);
        unsigned v1 = (unsigned)__ldg(mi + 32 + tid);
        int bad = __any_sync(FULLMASK, (v0 > 1u) || (v1 > 1u));
        if (tid == 0) g_mflag = bad;
    }

    if (idx < 768) {
        const float* row; const float* av; float* dst;
        if (idx < 192) {                 // w2 rows
            int t = idx >> 6, d = idx & 63;
            row = W + (t*D + d)*D;  av = a + t*128 + 64;  dst = g_U + t*64 + d;
        } else {                         // M1 rows
            int r = idx - 192; int v = r >> 6, d = r & 63; int s = v/3, t = v - s*3;
            row = W + (s*D + d)*D;  av = a + t*128;        dst = g_U + (3 + v)*64 + d;
        }
        *dst = dot64(row, av);
    }
}

// one butterfly level j over M slots of array p (16-lane transpose-reduce)
#define BF_LEVEL(p, M, j)                                                 \
    {                                                                     \
        const int sh_ = 1 << (j);                                         \
        const bool hi_ = ((lane >> (j)) & 1) != 0;                        \
        _Pragma("unroll")                                                 \
        for (int k = 0; k < ((M) >> ((j) + 1)); ++k) {                    \
            float keep_ = hi_ ? p[2*k+1] : p[2*k];                        \
            float send_ = hi_ ? p[2*k]   : p[2*k+1];                      \
            float recv_ = __shfl_xor_sync(FULLMASK, send_, sh_);          \
            p[k] = keep_ + recv_;                                         \
        }                                                                 \
    }

// ============ main: 64 threads (2 warps), 2 batches/warp, 4 batches/block, B/4 blocks ========
// Fully warp-independent; all h loaded in ONE burst; butterflies interleaved.
// __launch_bounds__(64, 9): cap regs at 112 -> 9 CTAs/SM (18 warps) vs 8 at 128 regs.
__global__ __launch_bounds__(64, 9) void hetgat_main(
    const float* __restrict__ h,      // (B, 22, 64)
    const void*  __restrict__ maskp,  // (3, B, 22)
    const float* __restrict__ W,      // (3, 64, 64): row k=t*64+d, h contiguous
    float* __restrict__ out,          // (B, 64)
    int B)
{
    __shared__ __align__(16) ull  s_c[4][96];        // per-batch coeffs [n*4 + t], (c,c)-packed
    __shared__ __align__(16) ull  s_g[4][192];       // per-batch g[k], (g,g)-packed

    const int tid  = threadIdx.x;
    const int wid  = tid >> 5;          // 0..1
    const int lane = tid & 31;
    const int half = lane >> 4;         // 0 = batch A, 1 = batch B
    const int L    = lane & 15;         // lane-in-half; also d-quad index
    const int bt   = wid*2 + half;      // batch slot in block, 0..3

    const bool u8m = (__ldg(&g_mflag) != 0);
    const int* mi32 = (const int*)maskp;
    const uint8_t* mu8 = (const uint8_t*)maskp;
    const size_t mT = (size_t)B * NN;

    const int b_raw = blockIdx.x * 4 + bt;
    const int b = (b_raw < B) ? b_raw : (B - 1);   // clamp for loads; store guarded

    // ---- slot -> (t, n) maps (proven R11-R13) ----
    const int sA1 = 16 + L;
    const int tA0 = L / 10,          nA0 = 1 + L % 10;
    const bool a1_ally  = (L <= 13);
    const bool a1_extra = (L == 14);
    const int tA1 = a1_ally ? (sA1 / 10) : 2;
    const int nA1 = a1_ally ? (1 + sA1 % 10) : 21;
    const int tO0 = (L < 11) ? 0 : 1,   nO0 = 11 + L - 11*tO0;
    const int tO1 = (sA1 < 22) ? 1 : 2, nO1 = 11 + sA1 - 11*tO1;

    // ---- mask prefetch (each half loads its own batch) ----
    const size_t boff = (size_t)b * NN;
    auto mld = [&](int t, int node) -> int {
        size_t i = (size_t)t * mT + boff + node;
        return u8m ? (int)mu8[i] : mi32[i];
    };
    const int mA0 = mld(tA0, nA0);
    const int mA1 = (L <= 14) ? mld(tA1, nA1) : 1;   // L15 dead -> masked
    const int mO0 = mld(tO0, nO0);
    const int mO1 = mld(tO1, nO1);
    const int mS  = (L < 3) ? mld(L, 0) : 0;

    // ---- w2 quads (lane owns d = 4L..4L+3; same across halves -> dedup) ----
    const float4 w2q0 = __ldg((const float4*)(g_U + 0*64) + L);
    const float4 w2q1 = __ldg((const float4*)(g_U + 1*64) + L);
    const float4 w2q2 = __ldg((const float4*)(g_U + 2*64) + L);

    const float4* hq = (const float4*)(h + (size_t)b * (NN*D));  // quad index = n*16 + L

    // ======== ALL DOTS in one h burst ========
    float p[32], r[32], q[16];
    {
        float4 h0 = __ldg(hq + L);   // n = 0
        #pragma unroll
        for (int v = 0; v < 9; ++v) {
            float4 mv = __ldg((const float4*)(g_U + (3 + v)*64) + L);
            q[v] = dot4(h0, mv);
        }
        #pragma unroll
        for (int v = 9; v < 16; ++v) q[v] = 0.f;
    }
    #pragma unroll
    for (int n = 1; n <= 10; ++n) {
        float4 hv = __ldg(hq + n*16 + L);
        p[n-1]  = dot4(hv, w2q0);
        p[9+n]  = dot4(hv, w2q1);
        p[19+n] = dot4(hv, w2q2);
    }
    #pragma unroll
    for (int n = 11; n <= 21; ++n) {
        float4 hv = __ldg(hq + n*16 + L);
        r[n-11] = dot4(hv, w2q0);
        r[n]    = dot4(hv, w2q1);
        if (n <= 20) r[11 + n] = dot4(hv, w2q2);
        else         p[30]     = dot4(hv, w2q2);   // opp(2,21) -> pass-1 slot 30
    }
    p[31] = 0.f;

    // ======== butterflies interleaved (3 independent shuffle chains) ========
    #pragma unroll
    for (int j = 0; j < 4; ++j) {
        BF_LEVEL(p, 32, j)
        BF_LEVEL(r, 32, j)
        BF_LEVEL(q, 16, j)
    }
    const float dA0 = p[0];   // ally slot L
    const float dA1 = p[1];   // slot 16+L (ally 16-29; L14: opp(2,21); L15: 0)
    const float dO0 = r[0];   // opp slot L
    const float dO1 = r[1];   // opp slot 16+L
    const float dS  = q[0];   // half-lane v<9 holds st[s*3+t]

    // ======== softmax (no max-subtraction; shift-invariant, logits small) ========
    float sA0_0 = __shfl_sync(FULLMASK, dS, tA0,     16);
    float sA0_1 = __shfl_sync(FULLMASK, dS, 3 + tA0, 16);
    float sA0_2 = __shfl_sync(FULLMASK, dS, 6 + tA0, 16);
    float sA1_0 = __shfl_sync(FULLMASK, dS, tA1,     16);
    float sA1_1 = __shfl_sync(FULLMASK, dS, 3 + tA1, 16);
    float sA1_2 = __shfl_sync(FULLMASK, dS, 6 + tA1, 16);
    float sO0_0 = __shfl_sync(FULLMASK, dS, tO0,     16);
    float sO0_1 = __shfl_sync(FULLMASK, dS, 3 + tO0, 16);
    float sO0_2 = __shfl_sync(FULLMASK, dS, 6 + tO0, 16);
    float sO1_0 = __shfl_sync(FULLMASK, dS, tO1,     16);
    float sO1_1 = __shfl_sync(FULLMASK, dS, 3 + tO1, 16);
    float sO1_2 = __shfl_sync(FULLMASK, dS, 6 + tO1, 16);

    float lsA0 = 0.f, lsA1 = 0.f, lsO0 = 0.f, lsO1 = 0.f;
    if (mA0 == 0) lsA0 = __expf(sA0_0 + dA0) + __expf(sA0_1 + dA0) + __expf(sA0_2 + dA0);
    if (mA1 == 0) lsA1 = __expf(sA1_0 + dA1) + __expf(sA1_1 + dA1) + __expf(sA1_2 + dA1);
    if (mO0 == 0) lsO0 = __expf(sO0_0 + dO0) + __expf(sO0_1 + dO0) + __expf(sO0_2 + dO0);
    if (mO1 == 0) lsO1 = __expf(sO1_0 + dO1) + __expf(sO1_1 + dO1) + __expf(sO1_2 + dO1);

    float sumA = lsA0 + (a1_ally  ? lsA1 : 0.f);
    float sumO = lsO0 + lsO1 + (a1_extra ? lsA1 : 0.f);
    #pragma unroll
    for (int off = 8; off >= 1; off >>= 1) {     // stays within half-warp
        sumA += __shfl_xor_sync(FULLMASK, sumA, off);
        sumO += __shfl_xor_sync(FULLMASK, sumO, off);
    }
    const float invA = __fdividef(1.f, sumA);
    const float invO = __fdividef(1.f, sumO);

    // ---- coefficient writes ((c,c)-packed), layout [n*4 + t] ----
    ull* sc = s_c[bt];
    sc[nA0*4 + tA0] = pack2((mA0 == 0) ? lsA0 * invA : 0.f);
    if (a1_ally)  sc[nA1*4 + tA1] = pack2((mA1 == 0) ? lsA1 * invA : 0.f);
    if (a1_extra) sc[21*4 + 2]    = pack2((mA1 == 0) ? lsA1 * invO : 0.f);
    sc[nO0*4 + tO0] = pack2((mO0 == 0) ? lsO0 * invO : 0.f);
    sc[nO1*4 + tO1] = pack2((mO1 == 0) ? lsO1 * invO : 0.f);
    if (L < 3) sc[0*4 + L] = pack2(mS ? 1.0f : 0.0f);
    __syncwarp();

    // ======== combine: g[t][quad] = sum_n c[t][n]*h[n][quad], packed FMA2 (h L1-hot) ========
    {
        const ull* scv = s_c[bt];
        const ulonglong2* hqu = (const ulonglong2*)(h + (size_t)b * (NN*D));
        ull g0x = 0, g0y = 0, g1x = 0, g1y = 0, g2x = 0, g2y = 0;
        #pragma unroll
        for (int n = 0; n < NN; ++n) {
            ulonglong2 hv = __ldg(hqu + n*16 + L);   // L1 hit
            ulonglong2 c01 = *(const ulonglong2*)&scv[n*4];   // c0, c1 (one LDS.128)
            ull c2 = scv[n*4 + 2];                            // c2 (LDS.64)
            g0x = fma2(c01.x, hv.x, g0x); g0y = fma2(c01.x, hv.y, g0y);
            g1x = fma2(c01.y, hv.x, g1x); g1y = fma2(c01.y, hv.y, g1y);
            g2x = fma2(c2,    hv.x, g2x); g2y = fma2(c2,    hv.y, g2y);
        }
        ulonglong2* d0 = (ulonglong2*)&s_g[bt][0*64 + 4*L];
        ulonglong2* d1 = (ulonglong2*)&s_g[bt][1*64 + 4*L];
        ulonglong2* d2 = (ulonglong2*)&s_g[bt][2*64 + 4*L];
        d0[0] = make_ulonglong2(pack2(lo32(g0x)), pack2(hi32(g0x)));
        d0[1] = make_ulonglong2(pack2(lo32(g0y)), pack2(hi32(g0y)));
        d1[0] = make_ulonglong2(pack2(lo32(g1x)), pack2(hi32(g1x)));
        d1[1] = make_ulonglong2(pack2(lo32(g1y)), pack2(hi32(g1y)));
        d2[0] = make_ulonglong2(pack2(lo32(g2x)), pack2(hi32(g2x)));
        d2[1] = make_ulonglong2(pack2(lo32(g2y)), pack2(hi32(g2y)));
    }
    __syncwarp();

    // ======== per-warp mat-vec, 4-way widened accumulators ========
    // lane covers cols 4L..4L+3; halves issue identical W addresses -> dedup.
    {
        ull acc[4][2];
        #pragma unroll
        for (int j = 0; j < 4; ++j) { acc[j][0] = 0ull; acc[j][1] = 0ull; }

        #pragma unroll 8
        for (int i = 0; i < 96; ++i) {           // 2 k per iter
            const int j = i & 3;
            ulonglong2 g2 = *(const ulonglong2*)&s_g[bt][2*i];   // g[2i], g[2i+1] dup-packed
            ulonglong2 w0 = __ldg((const ulonglong2*)(W + (2*i    )*D) + L);
            ulonglong2 w1 = __ldg((const ulonglong2*)(W + (2*i + 1)*D) + L);
            acc[j][0] = fma2(g2.x, w0.x, acc[j][0]); acc[j][1] = fma2(g2.x, w0.y, acc[j][1]);
            acc[j][0] = fma2(g2.y, w1.x, acc[j][0]); acc[j][1] = fma2(g2.y, w1.y, acc[j][1]);
        }
        ull a0 = add2(add2(acc[0][0], acc[1][0]), add2(acc[2][0], acc[3][0]));
        ull a1 = add2(add2(acc[0][1], acc[1][1]), add2(acc[2][1], acc[3][1]));

        if (b_raw < B) {
            float4 o;
            float r0 = lo32(a0), r1 = hi32(a0), r2 = lo32(a1), r3 = hi32(a1);
            o.x = (r0 > 0.f) ? r0 : expm1f(r0);
            o.y = (r1 > 0.f) ? r1 : expm1f(r1);
            o.z = (r2 > 0.f) ? r2 : expm1f(r2);
            o.w = (r3 > 0.f) ? r3 : expm1f(r3);
            *(float4*)(out + (size_t)b_raw * D + 4*L) = o;
        }
    }
}

extern "C" void kernel_launch(void* const* d_in, const int* in_sizes, int n_in,
                              void* d_out, int out_size)
{
    const float* h = nullptr;
    const void* mask = nullptr;
    const float* W = nullptr;
    const float* a = nullptr;
    long hsz = 0; int hidx = -1;
    for (int i = 0; i < n_in; ++i) {
        if (in_sizes[i] == 12288)      W = (const float*)d_in[i];
        else if (in_sizes[i] == 384)   a = (const float*)d_in[i];
        if ((long)in_sizes[i] > hsz) { hsz = in_sizes[i]; hidx = i; }
    }
    h = (const float*)d_in[hidx];
    const int B = (int)(hsz / (NN * D));
    for (int i = 0; i < n_in; ++i) {
        if (i != hidx && (long)in_sizes[i] == (long)3 * B * NN)
            mask = d_in[i];
    }

    hetgat_prep<<<6, 128>>>(W, a, mask);
    hetgat_main<<<(B + 3) / 4, 64>>>(h, mask, W, (float*)d_out, B);
}

// round 15
// speedup vs baseline: 1.0122x; 1.0122x over previous
#include <cuda_runtime.h>
#include <cstdint>

#define FULLMASK 0xffffffffu
using ull = unsigned long long;

constexpr int NN = 22;
constexpr int D  = 64;

// U table: rows 0-2 = w2[t][:] (= W[t] @ a[t,64:]), rows 3-11 = M1[s*3+t][:] (= W[s] @ a[t,:64])
__device__ __align__(16) float g_U[12*64];
__device__ int g_mflag;   // 1 => mask buffer is uint8, 0 => int32

__device__ __forceinline__ ull fma2(ull a, ull b, ull c) {
    ull d; asm("fma.rn.f32x2 %0, %1, %2, %3;" : "=l"(d) : "l"(a), "l"(b), "l"(c)); return d;
}
__device__ __forceinline__ ull add2(ull a, ull b) {
    ull d; asm("add.rn.f32x2 %0, %1, %2;" : "=l"(d) : "l"(a), "l"(b)); return d;
}
__device__ __forceinline__ ull pack2(float v) {
    ull r; asm("mov.b64 %0, {%1, %1};" : "=l"(r) : "f"(v)); return r;
}
__device__ __forceinline__ float lo32(ull v){ return __uint_as_float((unsigned)v); }
__device__ __forceinline__ float hi32(ull v){ return __uint_as_float((unsigned)(v >> 32)); }

__device__ __forceinline__ float dot4(float4 a, float4 b){
    return fmaf(a.w, b.w, fmaf(a.z, b.z, fmaf(a.y, b.y, a.x * b.x)));
}

__device__ __forceinline__ float dot64(const float* __restrict__ x, const float* __restrict__ y) {
    const float4* xp = (const float4*)x;
    const float4* yp = (const float4*)y;
    float a0 = 0.f, a1 = 0.f, a2 = 0.f, a3 = 0.f;
    #pragma unroll
    for (int k = 0; k < 16; ++k) {
        float4 u = __ldg(xp + k), v = __ldg(yp + k);
        a0 = fmaf(u.x, v.x, a0); a1 = fmaf(u.y, v.y, a1);
        a2 = fmaf(u.z, v.z, a2); a3 = fmaf(u.w, v.w, a3);
    }
    return (a0 + a1) + (a2 + a3);
}

// ================= prep: 6 blocks x 128, one thread per U entry =================
__global__ __launch_bounds__(128) void hetgat_prep(
    const float* __restrict__ W, const float* __restrict__ a,
    const void* __restrict__ maskp)
{
    const int tid = threadIdx.x;
    const int idx = blockIdx.x * 128 + tid;

    if (blockIdx.x == 0 && tid < 32) {
        const int* mi = (const int*)maskp;
        unsigned v0 = (unsigned)__ldg(mi + tid);
        unsigned v1 = (unsigned)__ldg(mi + 32 + tid);
        int bad = __any_sync(FULLMASK, (v0 > 1u) || (v1 > 1u));
        if (tid == 0) g_mflag = bad;
    }

    if (idx < 768) {
        const float* row; const float* av; float* dst;
        if (idx < 192) {                 // w2 rows
            int t = idx >> 6, d = idx & 63;
            row = W + (t*D + d)*D;  av = a + t*128 + 64;  dst = g_U + t*64 + d;
        } else {                         // M1 rows
            int r = idx - 192; int v = r >> 6, d = r & 63; int s = v/3, t = v - s*3;
            row = W + (s*D + d)*D;  av = a + t*128;        dst = g_U + (3 + v)*64 + d;
        }
        *dst = dot64(row, av);
    }
}

// one butterfly level j over M slots of array p (16-lane transpose-reduce)
#define BF_LEVEL(p, M, j)                                                 \
    {                                                                     \
        const int sh_ = 1 << (j);                                         \
        const bool hi_ = ((lane >> (j)) & 1) != 0;                        \
        _Pragma("unroll")                                                 \
        for (int k = 0; k < ((M) >> ((j) + 1)); ++k) {                    \
            float keep_ = hi_ ? p[2*k+1] : p[2*k];                        \
            float send_ = hi_ ? p[2*k]   : p[2*k+1];                      \
            float recv_ = __shfl_xor_sync(FULLMASK, send_, sh_);          \
            p[k] = keep_ + recv_;                                         \
        }                                                                 \
    }

// ============ main: 64 threads (2 warps), 2 batches/warp, 4 batches/block, B/4 blocks ========
// Fully warp-independent; all h loaded in ONE burst; butterflies interleaved.
// R13-proven configuration: 128 regs, 8 CTAs/SM (grid-limited to ~7), no spills.
__global__ __launch_bounds__(64, 8) void hetgat_main(
    const float* __restrict__ h,      // (B, 22, 64)
    const void*  __restrict__ maskp,  // (3, B, 22)
    const float* __restrict__ W,      // (3, 64, 64): row k=t*64+d, h contiguous
    float* __restrict__ out,          // (B, 64)
    int B)
{
    __shared__ __align__(16) ull  s_c[4][96];        // per-batch coeffs, (c,c)-packed
    __shared__ __align__(16) ull  s_g[4][192];       // per-batch g[k], (g,g)-packed

    const int tid  = threadIdx.x;
    const int wid  = tid >> 5;          // 0..1
    const int lane = tid & 31;
    const int half = lane >> 4;         // 0 = batch A, 1 = batch B
    const int L    = lane & 15;         // lane-in-half; also d-quad index
    const int bt   = wid*2 + half;      // batch slot in block, 0..3

    const bool u8m = (__ldg(&g_mflag) != 0);
    const int* mi32 = (const int*)maskp;
    const uint8_t* mu8 = (const uint8_t*)maskp;
    const size_t mT = (size_t)B * NN;

    const int b_raw = blockIdx.x * 4 + bt;
    const int b = (b_raw < B) ? b_raw : (B - 1);   // clamp for loads; store guarded

    // ---- slot -> (t, n) maps (proven R11-R13) ----
    const int sA1 = 16 + L;
    const int tA0 = L / 10,          nA0 = 1 + L % 10;
    const bool a1_ally  = (L <= 13);
    const bool a1_extra = (L == 14);
    const int tA1 = a1_ally ? (sA1 / 10) : 2;
    const int nA1 = a1_ally ? (1 + sA1 % 10) : 21;
    const int tO0 = (L < 11) ? 0 : 1,   nO0 = 11 + L - 11*tO0;
    const int tO1 = (sA1 < 22) ? 1 : 2, nO1 = 11 + sA1 - 11*tO1;

    // ---- mask prefetch (each half loads its own batch) ----
    const size_t boff = (size_t)b * NN;
    auto mld = [&](int t, int node) -> int {
        size_t i = (size_t)t * mT + boff + node;
        return u8m ? (int)mu8[i] : mi32[i];
    };
    const int mA0 = mld(tA0, nA0);
    const int mA1 = (L <= 14) ? mld(tA1, nA1) : 1;   // L15 dead -> masked
    const int mO0 = mld(tO0, nO0);
    const int mO1 = mld(tO1, nO1);
    const int mS  = (L < 3) ? mld(L, 0) : 0;

    // ---- w2 quads (lane owns d = 4L..4L+3; same across halves -> dedup) ----
    const float4 w2q0 = __ldg((const float4*)(g_U + 0*64) + L);
    const float4 w2q1 = __ldg((const float4*)(g_U + 1*64) + L);
    const float4 w2q2 = __ldg((const float4*)(g_U + 2*64) + L);

    const float4* hq = (const float4*)(h + (size_t)b * (NN*D));  // quad index = n*16 + L

    // ======== ALL DOTS in one h burst ========
    float p[32], r[32], q[16];
    {
        float4 h0 = __ldg(hq + L);   // n = 0
        #pragma unroll
        for (int v = 0; v < 9; ++v) {
            float4 mv = __ldg((const float4*)(g_U + (3 + v)*64) + L);
            q[v] = dot4(h0, mv);
        }
        #pragma unroll
        for (int v = 9; v < 16; ++v) q[v] = 0.f;
    }
    #pragma unroll
    for (int n = 1; n <= 10; ++n) {
        float4 hv = __ldg(hq + n*16 + L);
        p[n-1]  = dot4(hv, w2q0);
        p[9+n]  = dot4(hv, w2q1);
        p[19+n] = dot4(hv, w2q2);
    }
    #pragma unroll
    for (int n = 11; n <= 21; ++n) {
        float4 hv = __ldg(hq + n*16 + L);
        r[n-11] = dot4(hv, w2q0);
        r[n]    = dot4(hv, w2q1);
        if (n <= 20) r[11 + n] = dot4(hv, w2q2);
        else         p[30]     = dot4(hv, w2q2);   // opp(2,21) -> pass-1 slot 30
    }
    p[31] = 0.f;

    // ======== butterflies interleaved (3 independent shuffle chains) ========
    #pragma unroll
    for (int j = 0; j < 4; ++j) {
        BF_LEVEL(p, 32, j)
        BF_LEVEL(r, 32, j)
        BF_LEVEL(q, 16, j)
    }
    const float dA0 = p[0];   // ally slot L
    const float dA1 = p[1];   // slot 16+L (ally 16-29; L14: opp(2,21); L15: 0)
    const float dO0 = r[0];   // opp slot L
    const float dO1 = r[1];   // opp slot 16+L
    const float dS  = q[0];   // half-lane v<9 holds st[s*3+t]

    // ======== softmax (no max-subtraction; shift-invariant, logits small) ========
    float sA0_0 = __shfl_sync(FULLMASK, dS, tA0,     16);
    float sA0_1 = __shfl_sync(FULLMASK, dS, 3 + tA0, 16);
    float sA0_2 = __shfl_sync(FULLMASK, dS, 6 + tA0, 16);
    float sA1_0 = __shfl_sync(FULLMASK, dS, tA1,     16);
    float sA1_1 = __shfl_sync(FULLMASK, dS, 3 + tA1, 16);
    float sA1_2 = __shfl_sync(FULLMASK, dS, 6 + tA1, 16);
    float sO0_0 = __shfl_sync(FULLMASK, dS, tO0,     16);
    float sO0_1 = __shfl_sync(FULLMASK, dS, 3 + tO0, 16);
    float sO0_2 = __shfl_sync(FULLMASK, dS, 6 + tO0, 16);
    float sO1_0 = __shfl_sync(FULLMASK, dS, tO1,     16);
    float sO1_1 = __shfl_sync(FULLMASK, dS, 3 + tO1, 16);
    float sO1_2 = __shfl_sync(FULLMASK, dS, 6 + tO1, 16);

    float lsA0 = 0.f, lsA1 = 0.f, lsO0 = 0.f, lsO1 = 0.f;
    if (mA0 == 0) lsA0 = __expf(sA0_0 + dA0) + __expf(sA0_1 + dA0) + __expf(sA0_2 + dA0);
    if (mA1 == 0) lsA1 = __expf(sA1_0 + dA1) + __expf(sA1_1 + dA1) + __expf(sA1_2 + dA1);
    if (mO0 == 0) lsO0 = __expf(sO0_0 + dO0) + __expf(sO0_1 + dO0) + __expf(sO0_2 + dO0);
    if (mO1 == 0) lsO1 = __expf(sO1_0 + dO1) + __expf(sO1_1 + dO1) + __expf(sO1_2 + dO1);

    float sumA = lsA0 + (a1_ally  ? lsA1 : 0.f);
    float sumO = lsO0 + lsO1 + (a1_extra ? lsA1 : 0.f);
    #pragma unroll
    for (int off = 8; off >= 1; off >>= 1) {     // stays within half-warp
        sumA += __shfl_xor_sync(FULLMASK, sumA, off);
        sumO += __shfl_xor_sync(FULLMASK, sumO, off);
    }
    const float invA = __fdividef(1.f, sumA);
    const float invO = __fdividef(1.f, sumO);

    // ---- coefficient writes ((c,c)-packed), layout [t*32 + n] (R13-proven) ----
    ull* sc = s_c[bt];
    sc[tA0*32 + nA0] = pack2((mA0 == 0) ? lsA0 * invA : 0.f);
    if (a1_ally)  sc[tA1*32 + nA1] = pack2((mA1 == 0) ? lsA1 * invA : 0.f);
    if (a1_extra) sc[2*32 + 21]    = pack2((mA1 == 0) ? lsA1 * invO : 0.f);
    sc[tO0*32 + nO0] = pack2((mO0 == 0) ? lsO0 * invO : 0.f);
    sc[tO1*32 + nO1] = pack2((mO1 == 0) ? lsO1 * invO : 0.f);
    if (L < 3) sc[L*32 + 0] = pack2(mS ? 1.0f : 0.0f);
    __syncwarp();

    // ======== combine: g[t][quad] = sum_n c[t][n]*h[n][quad], packed FMA2 (h L1-hot) ========
    {
        const ull* scv = s_c[bt];
        const ulonglong2* hqu = (const ulonglong2*)(h + (size_t)b * (NN*D));
        ull g0x = 0, g0y = 0, g1x = 0, g1y = 0, g2x = 0, g2y = 0;
        #pragma unroll
        for (int n = 0; n < NN; ++n) {
            ulonglong2 hv = __ldg(hqu + n*16 + L);   // L1 hit
            ull c0 = scv[n], c1 = scv[32 + n], c2 = scv[64 + n];
            g0x = fma2(c0, hv.x, g0x); g0y = fma2(c0, hv.y, g0y);
            g1x = fma2(c1, hv.x, g1x); g1y = fma2(c1, hv.y, g1y);
            g2x = fma2(c2, hv.x, g2x); g2y = fma2(c2, hv.y, g2y);
        }
        ulonglong2* d0 = (ulonglong2*)&s_g[bt][0*64 + 4*L];
        ulonglong2* d1 = (ulonglong2*)&s_g[bt][1*64 + 4*L];
        ulonglong2* d2 = (ulonglong2*)&s_g[bt][2*64 + 4*L];
        d0[0] = make_ulonglong2(pack2(lo32(g0x)), pack2(hi32(g0x)));
        d0[1] = make_ulonglong2(pack2(lo32(g0y)), pack2(hi32(g0y)));
        d1[0] = make_ulonglong2(pack2(lo32(g1x)), pack2(hi32(g1x)));
        d1[1] = make_ulonglong2(pack2(lo32(g1y)), pack2(hi32(g1y)));
        d2[0] = make_ulonglong2(pack2(lo32(g2x)), pack2(hi32(g2x)));
        d2[1] = make_ulonglong2(pack2(lo32(g2y)), pack2(hi32(g2y)));
    }
    __syncwarp();

    // ======== per-warp mat-vec, 4-way widened accumulators, unroll 16 ========
    // lane covers cols 4L..4L+3; halves issue identical W addresses -> dedup.
    {
        ull acc[4][2];
        #pragma unroll
        for (int j = 0; j < 4; ++j) { acc[j][0] = 0ull; acc[j][1] = 0ull; }

        #pragma unroll 16
        for (int i = 0; i < 96; ++i) {           // 2 k per iter
            const int j = i & 3;
            ulonglong2 g2 = *(const ulonglong2*)&s_g[bt][2*i];   // g[2i], g[2i+1] dup-packed
            ulonglong2 w0 = __ldg((const ulonglong2*)(W + (2*i    )*D) + L);
            ulonglong2 w1 = __ldg((const ulonglong2*)(W + (2*i + 1)*D) + L);
            acc[j][0] = fma2(g2.x, w0.x, acc[j][0]); acc[j][1] = fma2(g2.x, w0.y, acc[j][1]);
            acc[j][0] = fma2(g2.y, w1.x, acc[j][0]); acc[j][1] = fma2(g2.y, w1.y, acc[j][1]);
        }
        ull a0 = add2(add2(acc[0][0], acc[1][0]), add2(acc[2][0], acc[3][0]));
        ull a1 = add2(add2(acc[0][1], acc[1][1]), add2(acc[2][1], acc[3][1]));

        if (b_raw < B) {
            float4 o;
            float r0 = lo32(a0), r1 = hi32(a0), r2 = lo32(a1), r3 = hi32(a1);
            o.x = (r0 > 0.f) ? r0 : expm1f(r0);
            o.y = (r1 > 0.f) ? r1 : expm1f(r1);
            o.z = (r2 > 0.f) ? r2 : expm1f(r2);
            o.w = (r3 > 0.f) ? r3 : expm1f(r3);
            *(float4*)(out + (size_t)b_raw * D + 4*L) = o;
        }
    }
}

extern "C" void kernel_launch(void* const* d_in, const int* in_sizes, int n_in,
                              void* d_out, int out_size)
{
    const float* h = nullptr;
    const void* mask = nullptr;
    const float* W = nullptr;
    const float* a = nullptr;
    long hsz = 0; int hidx = -1;
    for (int i = 0; i < n_in; ++i) {
        if (in_sizes[i] == 12288)      W = (const float*)d_in[i];
        else if (in_sizes[i] == 384)   a = (const float*)d_in[i];
        if ((long)in_sizes[i] > hsz) { hsz = in_sizes[i]; hidx = i; }
    }
    h = (const float*)d_in[hidx];
    const int B = (int)(hsz / (NN * D));
    for (int i = 0; i < n_in; ++i) {
        if (i != hidx && (long)in_sizes[i] == (long)3 * B * NN)
            mask = d_in[i];
    }

    hetgat_prep<<<6, 128>>>(W, a, mask);
    hetgat_main<<<(B + 3) / 4, 64>>>(h, mask, W, (float*)d_out, B);
}